// round 14
// baseline (speedup 1.0000x reference)
#include <cuda_runtime.h>

#define N3 262144
#define N2 65536
#define N1 16384

typedef unsigned long long u64;

// ---------------- scratch (allocation-free) ----------------
__device__ float g_x7p[N2 * 16];
__device__ float g_x7 [N2 * 32];
__device__ float g_x6 [N1 * 64];
__device__ float g_x7d[N2 * 32];
__device__ float g_P  [N2 * 288];   // 75MB, reused by every P phase (max = enc2)
__device__ float g_P6 [N3 * 9];     // head partial products

__device__ __forceinline__ u64 pack2(float lo, float hi) {
    u64 r; asm("mov.b64 %0, {%1, %2};" : "=l"(r) : "f"(lo), "f"(hi)); return r;
}
__device__ __forceinline__ void fma2(u64& d, u64 a, u64 b) {
    asm("fma.rn.f32x2 %0, %1, %2, %0;" : "+l"(d) : "l"(a), "l"(b));
}
__device__ __forceinline__ float4 max4(float4 a, float4 b) {
    return make_float4(fmaxf(a.x,b.x), fmaxf(a.y,b.y), fmaxf(a.z,b.z), fmaxf(a.w,b.w));
}

// ---------------- GEMM: P[M x Ntot] = A[M x K] @ B[K x Ntot] ----------------
// B[c][g] = w[g%COUT][(g/COUT)*K + c]   (per-tap weight transpose, built in smem)
// APOOL: A row r = elementwise max of child rows 4r..4r+3 (fused quadpool; inputs >=0).
// Tile: TM=128 x TN=144, 384 threads, 4 rows x 6 f32x2-col-pairs per thread.
// tx (=tid%12) owns col pairs at cols (2tx + 24j), j=0..5. B is staged PERMUTED so
// each thread's 6 pairs pack into 3 contiguous float4s:
//   BsP[c][m*48 + tx*4 + q] = B[c][2tx + 24*(2m + (q>>1)) + (q&1)],  m=0..2, q=0..3
// -> mainloop does 1 A LDS.128 + 3 B LDS.128 = 4 LDS instructions per kk
// (was 7 with 6x LDS.64) targeting the LSU/MIO instruction-dispatch limit.
template<int K, int COUT, bool APOOL>
__global__ __launch_bounds__(384, 2)
void gemm_k(const float* __restrict__ A, const float* __restrict__ w,
            float* __restrict__ P, int Ntot)
{
    extern __shared__ float smf[];
    float* As  = smf;             // [K][128] plain floats, transposed
    float* BsP = smf + K * 128;   // [K][144] permuted pairs

    const int tid  = threadIdx.x;
    const int row0 = blockIdx.x * 128;
    const int col0 = blockIdx.y * 144;

    // Stage A transposed: As[c][r] = A[row0+r][c]  (A is our aligned scratch -> float4 safe)
    const float4* A4 = reinterpret_cast<const float4*>(A);
    const int KC4 = K / 4;
    for (int idx = tid; idx < 128 * KC4; idx += 384) {
        int r = idx / KC4, c4 = idx % KC4;
        float4 v;
        if (APOOL) {
            size_t base = (size_t)(row0 + r) * 4 * KC4 + c4;
            v = __ldg(A4 + base);
            v = max4(v, __ldg(A4 + base + KC4));
            v = max4(v, __ldg(A4 + base + 2 * KC4));
            v = max4(v, __ldg(A4 + base + 3 * KC4));
        } else {
            v = __ldg(A4 + (size_t)(row0 + r) * KC4 + c4);
        }
        As[(c4 * 4 + 0) * 128 + r] = v.x;
        As[(c4 * 4 + 1) * 128 + r] = v.y;
        As[(c4 * 4 + 2) * 128 + r] = v.z;
        As[(c4 * 4 + 3) * 128 + r] = v.w;
    }
    // Stage B permuted (scalar loads from input buffer w)
    for (int idx = tid; idx < K * 144; idx += 384) {
        int c = idx / 144, t = idx % 144;
        int m = t / 48, r = t % 48;
        int px = r / 4, q = r % 4;                       // px = owner tx
        int col = 2 * px + 24 * (2 * m + (q >> 1)) + (q & 1);
        int g = col0 + col;
        BsP[idx] = __ldg(w + (g % COUT) * (9 * K) + (g / COUT) * K + c);
    }
    __syncthreads();

    const int tx = tid % 12;   // col-pair owner: cols 2tx+24j, j=0..5
    const int ty = tid / 12;   // 32 row-groups of 4

    u64 acc[4][6];
#pragma unroll
    for (int r = 0; r < 4; r++)
#pragma unroll
        for (int j = 0; j < 6; j++) acc[r][j] = 0ull;

#pragma unroll 4
    for (int kk = 0; kk < K; kk++) {
        // A fragment: 4 plain floats (1x LDS.128, broadcast across same-ty lanes)
        float4 Af = *reinterpret_cast<const float4*>(&As[kk * 128 + ty * 4]);
        float a[4] = {Af.x, Af.y, Af.z, Af.w};
        // B fragment: 3x LDS.128 -> 6 f32x2 pairs (j = 2m + h)
        const float* brow = &BsP[kk * 144 + tx * 4];
        float4 F0 = *reinterpret_cast<const float4*>(brow);
        float4 F1 = *reinterpret_cast<const float4*>(brow + 48);
        float4 F2 = *reinterpret_cast<const float4*>(brow + 96);
        u64 b2[6];
        b2[0] = reinterpret_cast<const u64*>(&F0)[0];
        b2[1] = reinterpret_cast<const u64*>(&F0)[1];
        b2[2] = reinterpret_cast<const u64*>(&F1)[0];
        b2[3] = reinterpret_cast<const u64*>(&F1)[1];
        b2[4] = reinterpret_cast<const u64*>(&F2)[0];
        b2[5] = reinterpret_cast<const u64*>(&F2)[1];
#pragma unroll
        for (int r = 0; r < 4; r++) {
            u64 ar = pack2(a[r], a[r]);   // JIT (a,a) pair on ALU pipe
#pragma unroll
            for (int j = 0; j < 6; j++)
                fma2(acc[r][j], ar, b2[j]);
        }
    }

#pragma unroll
    for (int r = 0; r < 4; r++) {
        float* dst = P + (size_t)(row0 + ty * 4 + r) * Ntot + col0 + tx * 2;
#pragma unroll
        for (int j = 0; j < 6; j++)
            *reinterpret_cast<u64*>(dst + j * 24) = acc[r][j];
    }
}

// ---------------- channel-parallel gather-sum ----------------
// thread = (node, 4 channels); COUT/4 consecutive threads cover a node's tap row
// -> each node-tap read is one contiguous COUT*4B transaction.
template<int COUT, int SHIFT, bool RELU>
__global__ __launch_bounds__(256)
void gather_k(const float* __restrict__ P, const int* __restrict__ neigh,
              const float* __restrict__ bias, float* __restrict__ out)
{
    constexpr int NPT = COUT / 4;     // threads per node
    constexpr int NPB = 256 / NPT;    // nodes per block
    __shared__ int sn[NPB * 9];
    const int node0 = blockIdx.x * NPB;
    for (int idx = threadIdx.x; idx < NPB * 9; idx += 256)
        sn[idx] = __ldg(neigh + (size_t)node0 * 9 + idx);
    __syncthreads();

    const int il = threadIdx.x / NPT, c4 = threadIdx.x % NPT;
    const int i = node0 + il;

    float4 v[9];
#pragma unroll
    for (int k = 0; k < 9; k++) {
        int n = sn[il * 9 + k];
        if (n >= 0)
            v[k] = __ldg(reinterpret_cast<const float4*>(
                       P + (size_t)(n >> SHIFT) * (9 * COUT) + k * COUT) + c4);
        else
            v[k] = make_float4(0.f, 0.f, 0.f, 0.f);
    }

    // bias: scalar loads (input buffer; avoid 16B-alignment assumption)
    float4 acc = make_float4(__ldg(bias + c4 * 4),     __ldg(bias + c4 * 4 + 1),
                             __ldg(bias + c4 * 4 + 2), __ldg(bias + c4 * 4 + 3));
#pragma unroll
    for (int k = 0; k < 9; k++) {
        acc.x += v[k].x; acc.y += v[k].y; acc.z += v[k].z; acc.w += v[k].w;
    }
    if (RELU) {
        acc.x = fmaxf(acc.x, 0.f); acc.y = fmaxf(acc.y, 0.f);
        acc.z = fmaxf(acc.z, 0.f); acc.w = fmaxf(acc.w, 0.f);
    }
    reinterpret_cast<float4*>(out + (size_t)i * COUT)[c4] = acc;
}

// ---------------- dec2 gather + fused head partial products ----------------
// COUT=16, SHIFT=2. Computes x8d slice in registers (relu), then the 9 head
// dots, butterfly-reduced over the node's 4 lanes; writes P6[i][0..8].
__global__ __launch_bounds__(256)
void gather_head_k(const float* __restrict__ P, const int* __restrict__ neigh,
                   const float* __restrict__ bias, const float* __restrict__ wh,
                   float* __restrict__ P6)
{
    constexpr int NPT = 4, NPB = 64;
    __shared__ int sn[NPB * 9];
    __shared__ float swh[144];
    const int node0 = blockIdx.x * NPB;
    for (int idx = threadIdx.x; idx < NPB * 9; idx += 256)
        sn[idx] = __ldg(neigh + (size_t)node0 * 9 + idx);
    if (threadIdx.x < 144) swh[threadIdx.x] = __ldg(wh + threadIdx.x);
    __syncthreads();

    const int il = threadIdx.x / NPT, c4 = threadIdx.x % NPT;
    const int i = node0 + il;

    float4 v[9];
#pragma unroll
    for (int k = 0; k < 9; k++) {
        int n = sn[il * 9 + k];
        if (n >= 0)
            v[k] = __ldg(reinterpret_cast<const float4*>(
                       P + (size_t)(n >> 2) * 144 + k * 16) + c4);
        else
            v[k] = make_float4(0.f, 0.f, 0.f, 0.f);
    }

    float4 acc = make_float4(__ldg(bias + c4 * 4),     __ldg(bias + c4 * 4 + 1),
                             __ldg(bias + c4 * 4 + 2), __ldg(bias + c4 * 4 + 3));
#pragma unroll
    for (int k = 0; k < 9; k++) {
        acc.x += v[k].x; acc.y += v[k].y; acc.z += v[k].z; acc.w += v[k].w;
    }
    acc.x = fmaxf(acc.x, 0.f); acc.y = fmaxf(acc.y, 0.f);
    acc.z = fmaxf(acc.z, 0.f); acc.w = fmaxf(acc.w, 0.f);

    // head partial dots: p[k2] = dot(acc, w_head[k2*16 + c4*4 .. +3])
    float p[9];
#pragma unroll
    for (int k2 = 0; k2 < 9; k2++) {
        const float* wv = &swh[k2 * 16 + c4 * 4];
        p[k2] = acc.x * wv[0] + acc.y * wv[1] + acc.z * wv[2] + acc.w * wv[3];
    }
    // butterfly across the 4 lanes of this node (lane groups are warp-aligned)
#pragma unroll
    for (int k2 = 0; k2 < 9; k2++) {
        p[k2] += __shfl_xor_sync(0xffffffffu, p[k2], 1);
        p[k2] += __shfl_xor_sync(0xffffffffu, p[k2], 2);
    }
    float* dst = P6 + (size_t)i * 9;
    dst[c4]     = p[c4];
    dst[c4 + 4] = p[c4 + 4];
    if (c4 == 0) dst[8] = p[8];
}

// ---------------- enc1 + pool3->2 fused: thread = parent node in N2 ----------------
__global__ __launch_bounds__(256)
void enc1pool_k(const float* __restrict__ feat, const int* __restrict__ neigh,
                const float* __restrict__ w, const float* __restrict__ b,
                float* __restrict__ out /* x7p [N2][16] */)
{
    __shared__ float sw[160];
    if (threadIdx.x < 144) sw[threadIdx.x] = __ldg(w + threadIdx.x);
    else if (threadIdx.x < 160) sw[threadIdx.x] = __ldg(b + threadIdx.x - 144);
    __syncthreads();

    int p = blockIdx.x * 256 + threadIdx.x;
    int nb[36];
#pragma unroll
    for (int j = 0; j < 36; j++) nb[j] = __ldg(neigh + (size_t)p * 36 + j);

    float m[16];
#pragma unroll
    for (int o = 0; o < 16; o++) m[o] = 0.f;   // relu(max(s)) with floor 0

#pragma unroll
    for (int ch = 0; ch < 4; ch++) {
        float f[9];
#pragma unroll
        for (int k = 0; k < 9; k++) {
            int n = nb[ch * 9 + k];
            f[k] = (n >= 0) ? __ldg(feat + n) : 0.f;
        }
#pragma unroll
        for (int o = 0; o < 16; o++) {
            float s = sw[144 + o];
#pragma unroll
            for (int k = 0; k < 9; k++) s += f[k] * sw[o * 9 + k];
            m[o] = fmaxf(m[o], s);
        }
    }
    float4* op = reinterpret_cast<float4*>(out + (size_t)p * 16);
#pragma unroll
    for (int j = 0; j < 4; j++)
        op[j] = make_float4(m[4*j], m[4*j+1], m[4*j+2], m[4*j+3]);
}

// ---------------- head gather: out[i] = b + sum_k P6[n_k][k] ----------------
__global__ __launch_bounds__(256)
void head_g(const float* __restrict__ P6, const int* __restrict__ neigh,
            const float* __restrict__ b, float* __restrict__ out)
{
    int i = blockIdx.x * 256 + threadIdx.x;
    float acc = __ldg(b);
#pragma unroll
    for (int k = 0; k < 9; k++) {
        int n = __ldg(neigh + (size_t)i * 9 + k);
        if (n >= 0) acc += __ldg(P6 + (size_t)n * 9 + k);
    }
    out[i] = acc;
}

extern "C" void kernel_launch(void* const* d_in, const int* in_sizes, int n_in,
                              void* d_out, int out_size)
{
    const float* features = (const float*)d_in[0];
    const int* neighs3 = (const int*)d_in[4];
    const int* neighs2 = (const int*)d_in[5];
    const int* neighs1 = (const int*)d_in[6];
    const float* w_enc1 = (const float*)d_in[7];
    const float* b_enc1 = (const float*)d_in[8];
    const float* w_enc2 = (const float*)d_in[9];
    const float* b_enc2 = (const float*)d_in[10];
    const float* w_enc3 = (const float*)d_in[11];
    const float* b_enc3 = (const float*)d_in[12];
    const float* w_dec1 = (const float*)d_in[13];
    const float* b_dec1 = (const float*)d_in[14];
    const float* w_dec2 = (const float*)d_in[15];
    const float* b_dec2 = (const float*)d_in[16];
    const float* w_head = (const float*)d_in[17];
    const float* b_head = (const float*)d_in[18];
    float* out = (float*)d_out;

    float *x7p, *x7, *x6, *x7d, *P, *P6;
    cudaGetSymbolAddress((void**)&x7p, g_x7p);
    cudaGetSymbolAddress((void**)&x7,  g_x7);
    cudaGetSymbolAddress((void**)&x6,  g_x6);
    cudaGetSymbolAddress((void**)&x7d, g_x7d);
    cudaGetSymbolAddress((void**)&P,   g_P);
    cudaGetSymbolAddress((void**)&P6,  g_P6);

    // dynamic smem: K*128*4 (plain A) + K*144*4 (permuted B)
    const int SM16 = 16 * 128 * 4 + 16 * 144 * 4;   // 17408
    const int SM32 = 32 * 128 * 4 + 32 * 144 * 4;   // 34816
    const int SM64 = 64 * 128 * 4 + 64 * 144 * 4;   // 69632
    cudaFuncSetAttribute(gemm_k<16, 32, false>, cudaFuncAttributeMaxDynamicSharedMemorySize, SM16);
    cudaFuncSetAttribute(gemm_k<32, 64, true>,  cudaFuncAttributeMaxDynamicSharedMemorySize, SM32);
    cudaFuncSetAttribute(gemm_k<64, 32, false>, cudaFuncAttributeMaxDynamicSharedMemorySize, SM64);
    cudaFuncSetAttribute(gemm_k<32, 16, false>, cudaFuncAttributeMaxDynamicSharedMemorySize, SM32);

    // enc1 + pool3->2 fused: features [N3,1] -> x7p [N2,16]
    enc1pool_k<<<N2 / 256, 256>>>(features, neighs3, w_enc1, b_enc1, x7p);
    // enc2: P = x7p[N2,16] @ B[16,288]; gather -> x7 [N2,32]
    gemm_k<16, 32, false><<<dim3(N2 / 128, 2), 384, SM16>>>(x7p, w_enc2, P, 288);
    gather_k<32, 0, true><<<N2 / 32, 256>>>(P, neighs2, b_enc2, x7);
    // enc3 (pool2->1 fused into A-stage): P = pool(x7)[N1,32] @ B[32,576]; gather -> x6 [N1,64]
    gemm_k<32, 64, true><<<dim3(N1 / 128, 4), 384, SM32>>>(x7, w_enc3, P, 576);
    gather_k<64, 0, true><<<N1 / 16, 256>>>(P, neighs1, b_enc3, x6);
    // dec1: P = x6[N1,64] @ B[64,288]; gather(unpool >>2) -> x7d [N2,32]
    gemm_k<64, 32, false><<<dim3(N1 / 128, 2), 384, SM64>>>(x6, w_dec1, P, 288);
    gather_k<32, 2, true><<<N2 / 32, 256>>>(P, neighs2, b_dec1, x7d);
    // dec2: P = x7d[N2,32] @ B[32,144]; gather(unpool >>2) + fused head dots -> P6 [N3,9]
    gemm_k<32, 16, false><<<dim3(N2 / 128, 1), 384, SM32>>>(x7d, w_dec2, P, 144);
    gather_head_k<<<N3 / 64, 256>>>(P, neighs3, b_dec2, w_head, P6);
    // head gather -> out [N3,1]
    head_g<<<N3 / 256, 256>>>(P6, neighs3, b_head, out);
}

// round 17
// speedup vs baseline: 1.0461x; 1.0461x over previous
#include <cuda_runtime.h>

#define N3 262144
#define N2 65536
#define N1 16384

typedef unsigned long long u64;
typedef unsigned int u32;

// ---------------- scratch (allocation-free) ----------------
__device__ float g_x7p[N2 * 16];
__device__ float g_x7 [N2 * 32];
__device__ float g_x6 [N1 * 64];
__device__ float g_x7d[N2 * 32];
__device__ float g_P  [N2 * 288];   // 75MB, reused by every P phase (max = enc2)
__device__ float g_P6 [N3 * 9];     // head partial products

__device__ __forceinline__ u64 pack2(float lo, float hi) {
    u64 r; asm("mov.b64 %0, {%1, %2};" : "=l"(r) : "f"(lo), "f"(hi)); return r;
}
__device__ __forceinline__ float4 max4(float4 a, float4 b) {
    return make_float4(fmaxf(a.x,b.x), fmaxf(a.y,b.y), fmaxf(a.z,b.z), fmaxf(a.w,b.w));
}
__device__ __forceinline__ void tf32_split(float x, u32& hi, u32& lo) {
    u32 h;
    asm("cvt.rna.tf32.f32 %0, %1;" : "=r"(h) : "f"(x));
    float l = x - __uint_as_float(h);
    u32 lb;
    asm("cvt.rna.tf32.f32 %0, %1;" : "=r"(lb) : "f"(l));
    hi = h; lo = lb;
}
// Warp MMA: D(16x8,f32) += A(16x8,tf32,row) * B(8x8,tf32,col)
__device__ __forceinline__ void mma8(float* c, const u32* a, u32 b0, u32 b1) {
    asm volatile(
        "mma.sync.aligned.m16n8k8.row.col.f32.tf32.tf32.f32 "
        "{%0,%1,%2,%3}, {%4,%5,%6,%7}, {%8,%9}, {%0,%1,%2,%3};"
        : "+f"(c[0]), "+f"(c[1]), "+f"(c[2]), "+f"(c[3])
        : "r"(a[0]), "r"(a[1]), "r"(a[2]), "r"(a[3]), "r"(b0), "r"(b1));
}

// ---------------- 3xTF32 mma.sync GEMM: P[M x Ntot] = A[M x K] @ B[K x Ntot] --
// Tile 128x144, 256 threads (8 warps x 16 rows x 144 cols).
// B[k][g] = w[(g%COUT)][(g/COUT)*K + k]. 3xTF32: D = Ah*Bh + Ah*Bl + Al*Bh.
// smem (u32): Ah/Al [128][K+4] (pad -> conflict-free A frags),
//             Bh/Bl [K][152]   (pad -> conflict-free B frags).
// APOOL: A row r = max of child rows 4r..4r+3 (fused quadpool; inputs >= 0).
template<int K, int COUT, bool APOOL>
__global__ __launch_bounds__(256)
void mma_gemm(const float* __restrict__ A, const float* __restrict__ w,
              float* __restrict__ P, int Ntot)
{
    constexpr int AP = K + 4;     // padded A row (floats)
    constexpr int BP = 152;       // padded B row (floats)
    extern __shared__ u32 smu[];
    u32* Ah = smu;
    u32* Al = Ah + 128 * AP;
    u32* Bh = Al + 128 * AP;
    u32* Bl = Bh + K * BP;

    const int tid  = threadIdx.x;
    const int row0 = blockIdx.x * 128;
    const int col0 = blockIdx.y * 144;

    // ---- stage A (tf32 hi/lo) ----
    const float4* A4 = reinterpret_cast<const float4*>(A);
    const int KC4 = K / 4;
    for (int idx = tid; idx < 128 * KC4; idx += 256) {
        int r = idx / KC4, c4 = idx % KC4;
        float4 v;
        if (APOOL) {
            size_t base = (size_t)(row0 + r) * 4 * KC4 + c4;
            v = __ldg(A4 + base);
            v = max4(v, __ldg(A4 + base + KC4));
            v = max4(v, __ldg(A4 + base + 2 * KC4));
            v = max4(v, __ldg(A4 + base + 3 * KC4));
        } else {
            v = __ldg(A4 + (size_t)(row0 + r) * KC4 + c4);
        }
        float comp[4] = {v.x, v.y, v.z, v.w};
#pragma unroll
        for (int j = 0; j < 4; j++) {
            u32 hi, lo; tf32_split(comp[j], hi, lo);
            Ah[r * AP + c4 * 4 + j] = hi;
            Al[r * AP + c4 * 4 + j] = lo;
        }
    }
    // ---- stage B (tf32 hi/lo): Bs[k][g] ----
    for (int idx = tid; idx < K * 144; idx += 256) {
        int k = idx / 144, g = idx % 144;
        int gg = col0 + g;
        float x = __ldg(w + (gg % COUT) * (9 * K) + (gg / COUT) * K + k);
        u32 hi, lo; tf32_split(x, hi, lo);
        Bh[k * BP + g] = hi;
        Bl[k * BP + g] = lo;
    }
    __syncthreads();

    const int wid = tid >> 5, lane = tid & 31;
    const int gid = lane >> 2, tig = lane & 3;
    const int rw = wid * 16;          // warp's row base within tile

    float acc[18][4];
#pragma unroll
    for (int nb = 0; nb < 18; nb++)
#pragma unroll
        for (int j = 0; j < 4; j++) acc[nb][j] = 0.f;

#pragma unroll
    for (int k8 = 0; k8 < K / 8; k8++) {
        const int k0 = k8 * 8;
        u32 ah[4], al[4];
        const int ra = rw + gid;
        ah[0] = Ah[(ra    ) * AP + k0 + tig];
        ah[1] = Ah[(ra + 8) * AP + k0 + tig];
        ah[2] = Ah[(ra    ) * AP + k0 + tig + 4];
        ah[3] = Ah[(ra + 8) * AP + k0 + tig + 4];
        al[0] = Al[(ra    ) * AP + k0 + tig];
        al[1] = Al[(ra + 8) * AP + k0 + tig];
        al[2] = Al[(ra    ) * AP + k0 + tig + 4];
        al[3] = Al[(ra + 8) * AP + k0 + tig + 4];
#pragma unroll
        for (int nb = 0; nb < 18; nb++) {
            u32 bh0 = Bh[(k0 + tig    ) * BP + nb * 8 + gid];
            u32 bh1 = Bh[(k0 + tig + 4) * BP + nb * 8 + gid];
            u32 bl0 = Bl[(k0 + tig    ) * BP + nb * 8 + gid];
            u32 bl1 = Bl[(k0 + tig + 4) * BP + nb * 8 + gid];
            mma8(acc[nb], ah, bh0, bh1);   // Ah*Bh
            mma8(acc[nb], ah, bl0, bl1);   // Ah*Bl
            mma8(acc[nb], al, bh0, bh1);   // Al*Bh
        }
    }

    // ---- epilogue: c0,c1 -> row gid; c2,c3 -> row gid+8; cols 2tig,2tig+1 ----
#pragma unroll
    for (int nb = 0; nb < 18; nb++) {
        size_t cidx = col0 + nb * 8 + 2 * tig;
        float* d0 = P + (size_t)(row0 + rw + gid    ) * Ntot + cidx;
        float* d1 = P + (size_t)(row0 + rw + gid + 8) * Ntot + cidx;
        *reinterpret_cast<u64*>(d0) = pack2(acc[nb][0], acc[nb][1]);
        *reinterpret_cast<u64*>(d1) = pack2(acc[nb][2], acc[nb][3]);
    }
}

// ---------------- channel-parallel gather-sum (unchanged, proven) ----------------
template<int COUT, int SHIFT, bool RELU>
__global__ __launch_bounds__(256)
void gather_k(const float* __restrict__ P, const int* __restrict__ neigh,
              const float* __restrict__ bias, float* __restrict__ out)
{
    constexpr int NPT = COUT / 4;
    constexpr int NPB = 256 / NPT;
    __shared__ int sn[NPB * 9];
    const int node0 = blockIdx.x * NPB;
    for (int idx = threadIdx.x; idx < NPB * 9; idx += 256)
        sn[idx] = __ldg(neigh + (size_t)node0 * 9 + idx);
    __syncthreads();

    const int il = threadIdx.x / NPT, c4 = threadIdx.x % NPT;
    const int i = node0 + il;

    float4 v[9];
#pragma unroll
    for (int k = 0; k < 9; k++) {
        int n = sn[il * 9 + k];
        if (n >= 0)
            v[k] = __ldg(reinterpret_cast<const float4*>(
                       P + (size_t)(n >> SHIFT) * (9 * COUT) + k * COUT) + c4);
        else
            v[k] = make_float4(0.f, 0.f, 0.f, 0.f);
    }

    float4 acc = make_float4(__ldg(bias + c4 * 4),     __ldg(bias + c4 * 4 + 1),
                             __ldg(bias + c4 * 4 + 2), __ldg(bias + c4 * 4 + 3));
#pragma unroll
    for (int k = 0; k < 9; k++) {
        acc.x += v[k].x; acc.y += v[k].y; acc.z += v[k].z; acc.w += v[k].w;
    }
    if (RELU) {
        acc.x = fmaxf(acc.x, 0.f); acc.y = fmaxf(acc.y, 0.f);
        acc.z = fmaxf(acc.z, 0.f); acc.w = fmaxf(acc.w, 0.f);
    }
    reinterpret_cast<float4*>(out + (size_t)i * COUT)[c4] = acc;
}

// ---------------- dec2 gather + fused head partial products (unchanged) ----------
__global__ __launch_bounds__(256)
void gather_head_k(const float* __restrict__ P, const int* __restrict__ neigh,
                   const float* __restrict__ bias, const float* __restrict__ wh,
                   float* __restrict__ P6)
{
    constexpr int NPT = 4, NPB = 64;
    __shared__ int sn[NPB * 9];
    __shared__ float swh[144];
    const int node0 = blockIdx.x * NPB;
    for (int idx = threadIdx.x; idx < NPB * 9; idx += 256)
        sn[idx] = __ldg(neigh + (size_t)node0 * 9 + idx);
    if (threadIdx.x < 144) swh[threadIdx.x] = __ldg(wh + threadIdx.x);
    __syncthreads();

    const int il = threadIdx.x / NPT, c4 = threadIdx.x % NPT;
    const int i = node0 + il;

    float4 v[9];
#pragma unroll
    for (int k = 0; k < 9; k++) {
        int n = sn[il * 9 + k];
        if (n >= 0)
            v[k] = __ldg(reinterpret_cast<const float4*>(
                       P + (size_t)(n >> 2) * 144 + k * 16) + c4);
        else
            v[k] = make_float4(0.f, 0.f, 0.f, 0.f);
    }

    float4 acc = make_float4(__ldg(bias + c4 * 4),     __ldg(bias + c4 * 4 + 1),
                             __ldg(bias + c4 * 4 + 2), __ldg(bias + c4 * 4 + 3));
#pragma unroll
    for (int k = 0; k < 9; k++) {
        acc.x += v[k].x; acc.y += v[k].y; acc.z += v[k].z; acc.w += v[k].w;
    }
    acc.x = fmaxf(acc.x, 0.f); acc.y = fmaxf(acc.y, 0.f);
    acc.z = fmaxf(acc.z, 0.f); acc.w = fmaxf(acc.w, 0.f);

    float p[9];
#pragma unroll
    for (int k2 = 0; k2 < 9; k2++) {
        const float* wv = &swh[k2 * 16 + c4 * 4];
        p[k2] = acc.x * wv[0] + acc.y * wv[1] + acc.z * wv[2] + acc.w * wv[3];
    }
#pragma unroll
    for (int k2 = 0; k2 < 9; k2++) {
        p[k2] += __shfl_xor_sync(0xffffffffu, p[k2], 1);
        p[k2] += __shfl_xor_sync(0xffffffffu, p[k2], 2);
    }
    float* dst = P6 + (size_t)i * 9;
    dst[c4]     = p[c4];
    dst[c4 + 4] = p[c4 + 4];
    if (c4 == 0) dst[8] = p[8];
}

// ---------------- enc1 + pool3->2 fused (unchanged) ----------------
__global__ __launch_bounds__(256)
void enc1pool_k(const float* __restrict__ feat, const int* __restrict__ neigh,
                const float* __restrict__ w, const float* __restrict__ b,
                float* __restrict__ out)
{
    __shared__ float sw[160];
    if (threadIdx.x < 144) sw[threadIdx.x] = __ldg(w + threadIdx.x);
    else if (threadIdx.x < 160) sw[threadIdx.x] = __ldg(b + threadIdx.x - 144);
    __syncthreads();

    int p = blockIdx.x * 256 + threadIdx.x;
    int nb[36];
#pragma unroll
    for (int j = 0; j < 36; j++) nb[j] = __ldg(neigh + (size_t)p * 36 + j);

    float m[16];
#pragma unroll
    for (int o = 0; o < 16; o++) m[o] = 0.f;

#pragma unroll
    for (int ch = 0; ch < 4; ch++) {
        float f[9];
#pragma unroll
        for (int k = 0; k < 9; k++) {
            int n = nb[ch * 9 + k];
            f[k] = (n >= 0) ? __ldg(feat + n) : 0.f;
        }
#pragma unroll
        for (int o = 0; o < 16; o++) {
            float s = sw[144 + o];
#pragma unroll
            for (int k = 0; k < 9; k++) s += f[k] * sw[o * 9 + k];
            m[o] = fmaxf(m[o], s);
        }
    }
    float4* op = reinterpret_cast<float4*>(out + (size_t)p * 16);
#pragma unroll
    for (int j = 0; j < 4; j++)
        op[j] = make_float4(m[4*j], m[4*j+1], m[4*j+2], m[4*j+3]);
}

// ---------------- head gather (unchanged) ----------------
__global__ __launch_bounds__(256)
void head_g(const float* __restrict__ P6, const int* __restrict__ neigh,
            const float* __restrict__ b, float* __restrict__ out)
{
    int i = blockIdx.x * 256 + threadIdx.x;
    float acc = __ldg(b);
#pragma unroll
    for (int k = 0; k < 9; k++) {
        int n = __ldg(neigh + (size_t)i * 9 + k);
        if (n >= 0) acc += __ldg(P6 + (size_t)n * 9 + k);
    }
    out[i] = acc;
}

extern "C" void kernel_launch(void* const* d_in, const int* in_sizes, int n_in,
                              void* d_out, int out_size)
{
    const float* features = (const float*)d_in[0];
    const int* neighs3 = (const int*)d_in[4];
    const int* neighs2 = (const int*)d_in[5];
    const int* neighs1 = (const int*)d_in[6];
    const float* w_enc1 = (const float*)d_in[7];
    const float* b_enc1 = (const float*)d_in[8];
    const float* w_enc2 = (const float*)d_in[9];
    const float* b_enc2 = (const float*)d_in[10];
    const float* w_enc3 = (const float*)d_in[11];
    const float* b_enc3 = (const float*)d_in[12];
    const float* w_dec1 = (const float*)d_in[13];
    const float* b_dec1 = (const float*)d_in[14];
    const float* w_dec2 = (const float*)d_in[15];
    const float* b_dec2 = (const float*)d_in[16];
    const float* w_head = (const float*)d_in[17];
    const float* b_head = (const float*)d_in[18];
    float* out = (float*)d_out;

    float *x7p, *x7, *x6, *x7d, *P, *P6;
    cudaGetSymbolAddress((void**)&x7p, g_x7p);
    cudaGetSymbolAddress((void**)&x7,  g_x7);
    cudaGetSymbolAddress((void**)&x6,  g_x6);
    cudaGetSymbolAddress((void**)&x7d, g_x7d);
    cudaGetSymbolAddress((void**)&P,   g_P);
    cudaGetSymbolAddress((void**)&P6,  g_P6);

    // dynamic smem: (2*128*(K+4) + 2*K*152) * 4 bytes
    const int SZ16 = (2 * 128 * 20 + 2 * 16 * 152) * 4;   // 39936
    const int SZ32 = (2 * 128 * 36 + 2 * 32 * 152) * 4;   // 75776
    const int SZ64 = (2 * 128 * 68 + 2 * 64 * 152) * 4;   // 147456
    cudaFuncSetAttribute(mma_gemm<16, 32, false>, cudaFuncAttributeMaxDynamicSharedMemorySize, SZ16);
    cudaFuncSetAttribute(mma_gemm<32, 64, true>,  cudaFuncAttributeMaxDynamicSharedMemorySize, SZ32);
    cudaFuncSetAttribute(mma_gemm<64, 32, false>, cudaFuncAttributeMaxDynamicSharedMemorySize, SZ64);
    cudaFuncSetAttribute(mma_gemm<32, 16, false>, cudaFuncAttributeMaxDynamicSharedMemorySize, SZ32);

    // enc1 + pool3->2 fused: features [N3,1] -> x7p [N2,16]
    enc1pool_k<<<N2 / 256, 256>>>(features, neighs3, w_enc1, b_enc1, x7p);
    // enc2: P = x7p[N2,16] @ B[16,288]; gather -> x7 [N2,32]
    mma_gemm<16, 32, false><<<dim3(N2 / 128, 2), 256, SZ16>>>(x7p, w_enc2, P, 288);
    gather_k<32, 0, true><<<N2 / 32, 256>>>(P, neighs2, b_enc2, x7);
    // enc3 (pool2->1 fused into A-stage): P = pool(x7)[N1,32] @ B[32,576]; gather -> x6 [N1,64]
    mma_gemm<32, 64, true><<<dim3(N1 / 128, 4), 256, SZ32>>>(x7, w_enc3, P, 576);
    gather_k<64, 0, true><<<N1 / 16, 256>>>(P, neighs1, b_enc3, x6);
    // dec1: P = x6[N1,64] @ B[64,288]; gather(unpool >>2) -> x7d [N2,32]
    mma_gemm<64, 32, false><<<dim3(N1 / 128, 2), 256, SZ64>>>(x6, w_dec1, P, 288);
    gather_k<32, 2, true><<<N2 / 32, 256>>>(P, neighs2, b_dec1, x7d);
    // dec2: P = x7d[N2,32] @ B[32,144]; gather(unpool >>2) + fused head dots -> P6 [N3,9]
    mma_gemm<32, 16, false><<<dim3(N2 / 128, 1), 256, SZ32>>>(x7d, w_dec2, P, 144);
    gather_head_k<<<N3 / 64, 256>>>(P, neighs3, b_dec2, w_head, P6);
    // head gather -> out [N3,1]
    head_g<<<N3 / 256, 256>>>(P6, neighs3, b_head, out);
}